// round 2
// baseline (speedup 1.0000x reference)
#include <cuda_runtime.h>
#include <math.h>

#define BB 16
#define SS 512
#define DD 512
#define VV 32000
#define KK 4
#define TT 64
#define NR (BB*KK)   // 64 rows
#define SOS_TOK 1
#define EOS_TOK 2
#define PAD_TOK 0
#define NEGV (-1e9f)

// ---------------- device state (scratch; no allocations allowed) ----------------
__device__ float g_encKT[BB*DD*SS];    // K-projected encoder, transposed: [b][e][s]  (16.8 MB)
__device__ float g_hT[DD*NR];          // h = e + ctx, transposed: [d][row]           (128 KB)
__device__ float g_logits[NR*VV];      // raw logits per row                          (8.2 MB)
__device__ float g_lse[NR];
__device__ float g_top_val[NR*KK];
__device__ int   g_top_idx[NR*KK];
__device__ int   g_tok[NR];            // last token per (b,k)
__device__ float g_scores[NR];
__device__ int   g_finished[NR];
__device__ int   g_seqs[BB*KK*TT];

// stable comparator matching jax.lax.top_k (desc value, ties -> lower index)
__device__ __forceinline__ bool better(float xv, int xi, float yv, int yi) {
    return (xv > yv) || (xv == yv && xi < yi);
}

// ---------------- kernel 0: encKT[b][e][s] = sum_d enc[b][s][d] * Wk[d][e] ----------------
__global__ void enck_kernel(const float* __restrict__ enc, const float* __restrict__ Wk) {
    int bs = blockIdx.x;               // b*SS + s
    int b = bs >> 9, s = bs & 511;
    int t = threadIdx.x;               // 256
    __shared__ float r_s[DD];
    r_s[t]       = enc[bs*DD + t];
    r_s[t + 256] = enc[bs*DD + t + 256];
    __syncthreads();
    for (int jj = t; jj < DD; jj += 256) {
        float acc = 0.f;
        #pragma unroll 8
        for (int d = 0; d < DD; ++d) acc += r_s[d] * Wk[d*DD + jj];
        g_encKT[(b*DD + jj)*SS + s] = acc;
    }
}

// ---------------- kernel 1: reset beam state ----------------
__global__ void init_kernel() {
    int t = threadIdx.x;   // 64
    g_tok[t] = SOS_TOK;
    g_finished[t] = 0;
    g_scores[t] = 0.f;
}

// ---------------- kernel 2: attention for one batch (all 4 beams) ----------------
__global__ void att_kernel(const float* __restrict__ enc, const int* __restrict__ lens,
                           const float* __restrict__ emb, const float* __restrict__ Wq) {
    int b = blockIdx.x;        // 16 blocks
    int t = threadIdx.x;       // 512 threads
    __shared__ float e_s[KK][DD];
    __shared__ float q_s[KK][DD];
    __shared__ float p_s[KK][SS];
    __shared__ float red[512];
    __shared__ float inv_s[KK];

    #pragma unroll
    for (int k = 0; k < KK; ++k) {
        int tok = g_tok[b*KK + k];
        e_s[k][t] = emb[tok*DD + t];
    }
    __syncthreads();

    // q = e @ Wq   (column t for all 4 beams)
    {
        float a0=0.f, a1=0.f, a2=0.f, a3=0.f;
        #pragma unroll 8
        for (int d = 0; d < DD; ++d) {
            float w = Wq[d*DD + t];
            a0 += e_s[0][d]*w; a1 += e_s[1][d]*w; a2 += e_s[2][d]*w; a3 += e_s[3][d]*w;
        }
        q_s[0][t]=a0; q_s[1][t]=a1; q_s[2][t]=a2; q_s[3][t]=a3;
    }
    __syncthreads();

    // attention scores (position t), masked, scaled
    int len = lens[b];
    const float scale = 0.044194173824159216f;  // 1/sqrt(512)
    if (t < len) {
        float a0=0.f, a1=0.f, a2=0.f, a3=0.f;
        #pragma unroll 8
        for (int e = 0; e < DD; ++e) {
            float kv = g_encKT[(b*DD + e)*SS + t];   // coalesced across t
            a0 += q_s[0][e]*kv; a1 += q_s[1][e]*kv; a2 += q_s[2][e]*kv; a3 += q_s[3][e]*kv;
        }
        p_s[0][t]=a0*scale; p_s[1][t]=a1*scale; p_s[2][t]=a2*scale; p_s[3][t]=a3*scale;
    } else {
        p_s[0][t]=NEGV; p_s[1][t]=NEGV; p_s[2][t]=NEGV; p_s[3][t]=NEGV;
    }
    __syncthreads();

    // softmax per beam
    for (int k = 0; k < KK; ++k) {
        red[t] = p_s[k][t];
        __syncthreads();
        for (int st = 256; st > 0; st >>= 1) {
            if (t < st) red[t] = fmaxf(red[t], red[t + st]);
            __syncthreads();
        }
        float m = red[0];
        __syncthreads();
        float ex = expf(p_s[k][t] - m);
        p_s[k][t] = ex;
        red[t] = ex;
        __syncthreads();
        for (int st = 256; st > 0; st >>= 1) {
            if (t < st) red[t] += red[t + st];
            __syncthreads();
        }
        if (t == 0) inv_s[k] = 1.f / red[0];
        __syncthreads();
    }

    // ctx (dim t) + h write (transposed layout for logits kernel)
    {
        float c0=0.f, c1=0.f, c2=0.f, c3=0.f;
        #pragma unroll 4
        for (int s = 0; s < SS; ++s) {
            float ev = enc[(b*SS + s)*DD + t];       // coalesced across t
            float p0=p_s[0][s], p1=p_s[1][s], p2=p_s[2][s], p3=p_s[3][s];
            c0 += p0*ev; c1 += p1*ev; c2 += p2*ev; c3 += p3*ev;
        }
        int base = b*KK;
        g_hT[t*NR + base + 0] = e_s[0][t] + c0*inv_s[0];
        g_hT[t*NR + base + 1] = e_s[1][t] + c1*inv_s[1];
        g_hT[t*NR + base + 2] = e_s[2][t] + c2*inv_s[2];
        g_hT[t*NR + base + 3] = e_s[3][t] + c3*inv_s[3];
    }
}

// ---------------- kernel 3: logits = H[64x512] @ Wfc[512x32000] + b ----------------
// 125 blocks x 256 threads; each thread owns one vocab column, all 64 rows in regs.
// All 64 H rows live in smem (128 KB) so Wfc streams through L2 exactly once per step.
__global__ void __launch_bounds__(256) logits_kernel(const float* __restrict__ Wfc,
                                                     const float* __restrict__ bfc) {
    extern __shared__ float h_s[];     // DD*NR floats = 128 KB, layout [d][row]
    int t = threadIdx.x;
    for (int i = t; i < DD*NR; i += 256) h_s[i] = g_hT[i];
    __syncthreads();

    int v = blockIdx.x*256 + t;
    float bias = bfc[v];
    float acc[NR];
    #pragma unroll
    for (int r = 0; r < NR; ++r) acc[r] = bias;

    #pragma unroll 2
    for (int d = 0; d < DD; ++d) {
        float w = Wfc[d*VV + v];                       // coalesced, L2-resident
        const float4* hp = (const float4*)(h_s + d*NR);
        #pragma unroll
        for (int rq = 0; rq < NR/4; ++rq) {            // 16x LDS.128 broadcast
            float4 hv = hp[rq];
            acc[rq*4+0] = fmaf(hv.x, w, acc[rq*4+0]);
            acc[rq*4+1] = fmaf(hv.y, w, acc[rq*4+1]);
            acc[rq*4+2] = fmaf(hv.z, w, acc[rq*4+2]);
            acc[rq*4+3] = fmaf(hv.w, w, acc[rq*4+3]);
        }
    }
    #pragma unroll
    for (int r = 0; r < NR; ++r) g_logits[r*VV + v] = acc[r];
}

// ---------------- kernel 4: per-row logsumexp + stable top-4 ----------------
__global__ void reduce_kernel() {
    int row = blockIdx.x;      // 64
    int t = threadIdx.x;       // 256
    const float* L = g_logits + row*VV;

    float m = -3.4e38f, s = 0.f;
    float tv0=-3.4e38f, tv1=-3.4e38f, tv2=-3.4e38f, tv3=-3.4e38f;
    int   ti0=0x7fffffff, ti1=0x7fffffff, ti2=0x7fffffff, ti3=0x7fffffff;

    for (int v = t; v < VV; v += 256) {
        float x = L[v];
        if (x > m) { s = s*expf(m - x) + 1.f; m = x; }
        else       { s += expf(x - m); }
        if (better(x, v, tv3, ti3)) {
            if (better(x, v, tv0, ti0))      { tv3=tv2;ti3=ti2; tv2=tv1;ti2=ti1; tv1=tv0;ti1=ti0; tv0=x;ti0=v; }
            else if (better(x, v, tv1, ti1)) { tv3=tv2;ti3=ti2; tv2=tv1;ti2=ti1; tv1=x;ti1=v; }
            else if (better(x, v, tv2, ti2)) { tv3=tv2;ti3=ti2; tv2=x;ti2=v; }
            else                             { tv3=x;ti3=v; }
        }
    }

    __shared__ float sm[256], ssum[256];
    __shared__ float stv[256][4];
    __shared__ int   sti[256][4];
    sm[t]=m; ssum[t]=s;
    stv[t][0]=tv0; stv[t][1]=tv1; stv[t][2]=tv2; stv[t][3]=tv3;
    sti[t][0]=ti0; sti[t][1]=ti1; sti[t][2]=ti2; sti[t][3]=ti3;
    __syncthreads();

    for (int st = 128; st > 0; st >>= 1) {
        if (t < st) {
            // merge logsumexp partials
            float m2 = sm[t+st], s2 = ssum[t+st];
            float M = fmaxf(sm[t], m2);
            ssum[t] = ssum[t]*expf(sm[t]-M) + s2*expf(m2-M);
            sm[t] = M;
            // merge two sorted top-4 lists
            float av[4], bv2[4], ov[4];
            int   ai[4], bi2[4], oi[4];
            #pragma unroll
            for (int j = 0; j < 4; ++j) { av[j]=stv[t][j]; ai[j]=sti[t][j];
                                          bv2[j]=stv[t+st][j]; bi2[j]=sti[t+st][j]; }
            int i = 0, j2 = 0;
            #pragma unroll
            for (int o = 0; o < 4; ++o) {
                bool ta = (j2 >= 4) || (i < 4 && better(av[i], ai[i], bv2[j2], bi2[j2]));
                if (ta) { ov[o]=av[i]; oi[o]=ai[i]; ++i; }
                else    { ov[o]=bv2[j2]; oi[o]=bi2[j2]; ++j2; }
            }
            #pragma unroll
            for (int o = 0; o < 4; ++o) { stv[t][o]=ov[o]; sti[t][o]=oi[o]; }
        }
        __syncthreads();
    }

    if (t == 0) {
        g_lse[row] = sm[0] + logf(ssum[0]);
        #pragma unroll
        for (int j = 0; j < 4; ++j) {
            g_top_val[row*KK + j] = stv[0][j];
            g_top_idx[row*KK + j] = sti[0][j];
        }
    }
}

// ---------------- kernel 5a: initialize beams from the SOS step (t=1) ----------------
__global__ void init_combine_kernel() {
    int b = blockIdx.x;     // 16
    int t = threadIdx.x;    // 64
    int row = b*KK;         // SOS was decoded in beam slot k=0 (all slots identical)
    if (t < KK) {
        int tok = g_top_idx[row*KK + t];
        g_scores[b*KK + t]   = g_top_val[row*KK + t] - g_lse[row];
        g_tok[b*KK + t]      = tok;
        g_finished[b*KK + t] = (tok == EOS_TOK) ? 1 : 0;
    }
    for (int i = t; i < KK*TT; i += 64) {
        int k = i >> 6, j = i & 63;
        int v = (j == 0) ? SOS_TOK : (j == 1 ? g_top_idx[row*KK + k] : PAD_TOK);
        g_seqs[b*KK*TT + i] = v;
    }
}

// ---------------- kernel 5b: beam combine for step t (2..63) ----------------
__global__ void combine_kernel(int tstep) {
    int b = blockIdx.x;     // 16
    int t = threadIdx.x;    // 64
    __shared__ float cl[KK*KK];
    __shared__ int   cv[KK*KK];
    __shared__ int   nbeam[KK], ntok[KK], nfin[KK];
    __shared__ float nsc[KK];
    __shared__ int   oldseq[KK][TT];
    __shared__ int   oldfin[KK];
    __shared__ float oldsc[KK];

    if (t < KK) { oldfin[t] = g_finished[b*KK + t]; oldsc[t] = g_scores[b*KK + t]; }
    for (int i = t; i < KK*TT; i += 64) oldseq[i >> 6][i & 63] = g_seqs[b*KK*TT + i];
    __syncthreads();

    if (t == 0) {
        for (int k = 0; k < KK; ++k) {
            int row = b*KK + k;
            if (oldfin[k]) {
                cl[k*KK+0] = 0.f; cv[k*KK+0] = PAD_TOK;
                for (int j = 1; j < KK; ++j) { cl[k*KK+j] = NEGV; cv[k*KK+j] = PAD_TOK; }
            } else {
                float lse = g_lse[row];
                for (int j = 0; j < KK; ++j) {
                    cl[k*KK+j] = g_top_val[row*KK + j] - lse;
                    cv[k*KK+j] = g_top_idx[row*KK + j];
                }
            }
        }
        float total[KK*KK];
        for (int i = 0; i < KK*KK; ++i) total[i] = oldsc[i >> 2] + cl[i];
        bool used[KK*KK] = {false};
        for (int k = 0; k < KK; ++k) {
            int best = -1;
            for (int i = 0; i < KK*KK; ++i)
                if (!used[i] && (best < 0 || total[i] > total[best])) best = i;  // ties -> lower idx
            used[best] = true;
            int beam = best >> 2;
            nbeam[k] = beam;
            ntok[k]  = cv[best];
            nsc[k]   = total[best];
            nfin[k]  = oldfin[beam] | (cv[best] == EOS_TOK ? 1 : 0);
        }
    }
    __syncthreads();

    if (t < KK) {
        g_scores[b*KK + t]   = nsc[t];
        g_finished[b*KK + t] = nfin[t];
        g_tok[b*KK + t]      = ntok[t];
    }
    for (int i = t; i < KK*TT; i += 64) {
        int k = i >> 6, j = i & 63;
        g_seqs[b*KK*TT + i] = (j == tstep) ? ntok[k] : oldseq[nbeam[k]][j];
    }
}

// ---------------- kernel 6: pick best hypothesis, write output ----------------
__global__ void out_kernel(float* __restrict__ out, int out_size) {
    int b = blockIdx.x;     // 16
    int t = threadIdx.x;    // 64
    __shared__ int best;
    __shared__ float bestsc;
    if (t == 0) {
        int bi = 0; float bs = g_scores[b*KK];
        for (int k = 1; k < KK; ++k)
            if (g_scores[b*KK + k] > bs) { bs = g_scores[b*KK + k]; bi = k; }
        best = bi; bestsc = bs;
    }
    __syncthreads();
    if (out_size >= BB*TT + BB) {
        out[b*TT + t] = (float)g_seqs[b*KK*TT + best*TT + t];
        if (t == 0) out[BB*TT + b] = bestsc;
    } else if (out_size == BB*TT) {
        out[b*TT + t] = (float)g_seqs[b*KK*TT + best*TT + t];
    } else if (out_size == BB) {
        if (t == 0) out[b] = bestsc;
    }
}

// ---------------- launcher ----------------
extern "C" void kernel_launch(void* const* d_in, const int* in_sizes, int n_in,
                              void* d_out, int out_size) {
    const float* enc  = (const float*)d_in[0];
    const int*   lens = (const int*)  d_in[1];
    const float* emb  = (const float*)d_in[2];
    const float* Wq   = (const float*)d_in[3];
    const float* Wk   = (const float*)d_in[4];
    const float* Wfc  = (const float*)d_in[5];
    const float* bfc  = (const float*)d_in[6];

    cudaFuncSetAttribute(logits_kernel, cudaFuncAttributeMaxDynamicSharedMemorySize,
                         DD*NR*(int)sizeof(float));

    enck_kernel<<<BB*SS, 256>>>(enc, Wk);
    init_kernel<<<1, 64>>>();

    // step 1: decode from SOS, expand to K beams
    att_kernel<<<BB, 512>>>(enc, lens, emb, Wq);
    logits_kernel<<<VV/256, 256, DD*NR*(int)sizeof(float)>>>(Wfc, bfc);
    reduce_kernel<<<NR, 256>>>();
    init_combine_kernel<<<BB, 64>>>();

    // steps 2..63
    for (int step = 2; step < TT; ++step) {
        att_kernel<<<BB, 512>>>(enc, lens, emb, Wq);
        logits_kernel<<<VV/256, 256, DD*NR*(int)sizeof(float)>>>(Wfc, bfc);
        reduce_kernel<<<NR, 256>>>();
        combine_kernel<<<BB, 64>>>(step);
    }

    out_kernel<<<BB, 64>>>((float*)d_out, out_size);
}

// round 3
// speedup vs baseline: 1.6792x; 1.6792x over previous
#include <cuda_runtime.h>
#include <math.h>

#define BB 16
#define SS 512
#define DD 512
#define VV 32000
#define KK 4
#define TT 64
#define NR (BB*KK)     // 64 rows
#define NCG (VV/256)   // 125 vocab col-groups of 256
#define SOS_TOK 1
#define EOS_TOK 2
#define PAD_TOK 0
#define NEGV (-1e9f)

// ---------------- device state ----------------
__device__ float g_encKT[BB*DD*SS];    // [b][e][s]
__device__ float g_hT[DD*NR];          // [d][row]
__device__ float g_pmax[NR*NCG];       // per (row, colgroup) partials
__device__ float g_psum[NR*NCG];
__device__ float g_pval[NR*NCG*4];
__device__ int   g_pidx[NR*NCG*4];
__device__ int   g_tok[NR];
__device__ float g_scores[NR];
__device__ int   g_finished[NR];
__device__ int   g_seqs[BB*KK*TT];

__device__ __forceinline__ bool better(float xv, int xi, float yv, int yi) {
    return (xv > yv) || (xv == yv && xi < yi);
}

#define FMA2(acc,a,b) asm("fma.rn.f32x2 %0, %1, %2, %3;" : "=l"(acc) : "l"(a), "l"(b), "l"(acc))
#define PACK2(d,x,y)  asm("mov.b64 %0, {%1, %2};" : "=l"(d) : "f"(x), "f"(y))
#define UNPACK2(x,y,d) asm("mov.b64 {%0, %1}, %2;" : "=f"(x), "=f"(y) : "l"(d))

// merge two sorted (desc val, asc idx) top-4 lists -> a
__device__ __forceinline__ void merge4(float av[4], int ai[4], const float bv[4], const int bi[4]) {
    float ov[4]; int oi[4]; int i = 0, j = 0;
    #pragma unroll
    for (int o = 0; o < 4; ++o) {
        bool ta = (j >= 4) || (i < 4 && better(av[i], ai[i], bv[j], bi[j]));
        if (ta) { ov[o] = av[i]; oi[o] = ai[i]; ++i; }
        else    { ov[o] = bv[j]; oi[o] = bi[j]; ++j; }
    }
    #pragma unroll
    for (int o = 0; o < 4; ++o) { av[o] = ov[o]; ai[o] = oi[o]; }
}

__device__ __forceinline__ void insert4(float av[4], int ai[4], float x, int xi) {
    if (better(x, xi, av[3], ai[3])) {
        if (better(x, xi, av[0], ai[0]))      { av[3]=av[2];ai[3]=ai[2]; av[2]=av[1];ai[2]=ai[1]; av[1]=av[0];ai[1]=ai[0]; av[0]=x;ai[0]=xi; }
        else if (better(x, xi, av[1], ai[1])) { av[3]=av[2];ai[3]=ai[2]; av[2]=av[1];ai[2]=ai[1]; av[1]=x;ai[1]=xi; }
        else if (better(x, xi, av[2], ai[2])) { av[3]=av[2];ai[3]=ai[2]; av[2]=x;ai[2]=xi; }
        else                                  { av[3]=x;ai[3]=xi; }
    }
}

// ---------------- kernel 0: encKT[b][e][s] ----------------
__global__ void enck_kernel(const float* __restrict__ enc, const float* __restrict__ Wk) {
    int bs = blockIdx.x;
    int b = bs >> 9, s = bs & 511;
    int t = threadIdx.x;               // 256
    __shared__ float r_s[DD];
    r_s[t]       = enc[bs*DD + t];
    r_s[t + 256] = enc[bs*DD + t + 256];
    __syncthreads();
    for (int jj = t; jj < DD; jj += 256) {
        float acc = 0.f;
        #pragma unroll 8
        for (int d = 0; d < DD; ++d) acc += r_s[d] * Wk[d*DD + jj];
        g_encKT[(b*DD + jj)*SS + s] = acc;
    }
}

__global__ void init_kernel() {
    int t = threadIdx.x;   // 64
    g_tok[t] = SOS_TOK;
    g_finished[t] = 0;
    g_scores[t] = 0.f;
}

// ---------------- kernel 2: attention, one block per (b,k) ----------------
__global__ void __launch_bounds__(512) att_kernel(const float* __restrict__ enc,
                                                  const int* __restrict__ lens,
                                                  const float* __restrict__ emb,
                                                  const float* __restrict__ Wq) {
    int row = blockIdx.x;          // 64
    int b = row >> 2;
    int t = threadIdx.x;           // 512
    __shared__ float e_s[DD];
    __shared__ float q_s[DD];
    __shared__ float p_s[SS];
    __shared__ float red[512];

    int tok = g_tok[row];
    e_s[t] = emb[tok*DD + t];
    __syncthreads();

    // q[t] = sum_d e[d] * Wq[d][t]
    {
        float a = 0.f;
        #pragma unroll 8
        for (int d = 0; d < DD; ++d) a += e_s[d] * Wq[d*DD + t];
        q_s[t] = a;
    }
    __syncthreads();

    // attention score at position t
    int len = lens[b];
    const float scale = 0.044194173824159216f;
    float sc;
    if (t < len) {
        float a = 0.f;
        #pragma unroll 8
        for (int e = 0; e < DD; ++e) a += q_s[e] * g_encKT[(b*DD + e)*SS + t];
        sc = a * scale;
    } else sc = NEGV;
    p_s[t] = sc;
    red[t] = sc;
    __syncthreads();
    #pragma unroll
    for (int st = 256; st > 0; st >>= 1) {
        if (t < st) red[t] = fmaxf(red[t], red[t + st]);
        __syncthreads();
    }
    float m = red[0];
    __syncthreads();
    float ex = expf(sc - m);
    p_s[t] = ex;
    red[t] = ex;
    __syncthreads();
    #pragma unroll
    for (int st = 256; st > 0; st >>= 1) {
        if (t < st) red[t] += red[t + st];
        __syncthreads();
    }
    float inv = 1.f / red[0];
    __syncthreads();

    // ctx[t] = sum_s p[s] * enc[b][s][t]
    {
        float a = 0.f;
        #pragma unroll 8
        for (int s = 0; s < SS; ++s) a += p_s[s] * enc[(b*SS + s)*DD + t];
        g_hT[t*NR + row] = e_s[t] + a*inv;
    }
}

// ---------------- kernel 3: logits GEMM (f32x2) + fused per-block reduction ----------------
// grid = 250 (= 2 rowgroups x 125 colgroups), 256 threads, 64KB dyn smem.
__global__ void __launch_bounds__(256) logits_kernel(const float* __restrict__ Wfc,
                                                     const float* __restrict__ bfc) {
    extern __shared__ float h_s[];         // [512][32] floats = 64 KB
    int rg = blockIdx.x & 1;
    int cg = blockIdx.x >> 1;
    int t = threadIdx.x;

    for (int i = t; i < DD*32; i += 256) {
        int d = i >> 5, r = i & 31;
        h_s[i] = g_hT[d*NR + rg*32 + r];
    }
    __syncthreads();

    int v = cg*256 + t;
    float bias = bfc[v];
    unsigned long long acc[16];
    unsigned long long bias2; PACK2(bias2, bias, bias);
    #pragma unroll
    for (int j = 0; j < 16; ++j) acc[j] = bias2;

    #pragma unroll 4
    for (int d = 0; d < DD; ++d) {
        float w = Wfc[d*VV + v];
        unsigned long long w2; PACK2(w2, w, w);
        const ulonglong2* hp = (const ulonglong2*)(h_s + d*32);
        #pragma unroll
        for (int j = 0; j < 8; ++j) {
            ulonglong2 hv = hp[j];          // rows 4j..4j+3
            FMA2(acc[2*j],   hv.x, w2);
            FMA2(acc[2*j+1], hv.y, w2);
        }
    }

    // unpack to 32 row values for vocab column v
    float vals[32];
    #pragma unroll
    for (int j = 0; j < 16; ++j) { float lo, hi; UNPACK2(lo, hi, acc[j]); vals[2*j] = lo; vals[2*j+1] = hi; }

    __syncthreads();                        // done reading h tile; reuse smem
    float* sv = h_s;                        // [32][257]
    #pragma unroll
    for (int r = 0; r < 32; ++r) sv[r*257 + t] = vals[r];
    __syncthreads();

    // warp w reduces rows 4w..4w+3 over this block's 256 columns
    int w = t >> 5, l = t & 31;
    #pragma unroll
    for (int rr = 0; rr < 4; ++rr) {
        int r = w*4 + rr;
        float x[8]; int xi[8];
        #pragma unroll
        for (int i = 0; i < 8; ++i) { x[i] = sv[r*257 + l + 32*i]; xi[i] = cg*256 + l + 32*i; }
        float m = x[0];
        #pragma unroll
        for (int i = 1; i < 8; ++i) m = fmaxf(m, x[i]);
        #pragma unroll
        for (int off = 16; off > 0; off >>= 1) m = fmaxf(m, __shfl_xor_sync(0xffffffffu, m, off));
        float s = 0.f;
        #pragma unroll
        for (int i = 0; i < 8; ++i) s += expf(x[i] - m);
        #pragma unroll
        for (int off = 16; off > 0; off >>= 1) s += __shfl_xor_sync(0xffffffffu, s, off);
        float tv[4] = {-3.4e38f, -3.4e38f, -3.4e38f, -3.4e38f};
        int   ti[4] = {0x7fffffff, 0x7fffffff, 0x7fffffff, 0x7fffffff};
        #pragma unroll
        for (int i = 0; i < 8; ++i) insert4(tv, ti, x[i], xi[i]);
        #pragma unroll
        for (int off = 16; off > 0; off >>= 1) {
            float bv[4]; int bi[4];
            #pragma unroll
            for (int j = 0; j < 4; ++j) {
                bv[j] = __shfl_xor_sync(0xffffffffu, tv[j], off);
                bi[j] = __shfl_xor_sync(0xffffffffu, ti[j], off);
            }
            merge4(tv, ti, bv, bi);
        }
        if (l == 0) {
            int grow = rg*32 + r;
            int p = grow*NCG + cg;
            g_pmax[p] = m;
            g_psum[p] = s;
            #pragma unroll
            for (int j = 0; j < 4; ++j) { g_pval[p*4+j] = tv[j]; g_pidx[p*4+j] = ti[j]; }
        }
    }
}

// ---------------- kernel 4: merge partials + beam combine ----------------
// grid 16 (batch), 128 threads (warp k merges row b*4+k)
__global__ void __launch_bounds__(128) combine_kernel(int tstep) {
    int b = blockIdx.x;
    int t = threadIdx.x;
    int w = t >> 5, l = t & 31;
    __shared__ float s_lse[KK];
    __shared__ float s_tv[KK][KK];
    __shared__ int   s_ti[KK][KK];
    __shared__ int   nbeam[KK], ntok[KK], nfin[KK];
    __shared__ float nsc[KK];
    __shared__ int   oldseq[KK][TT];
    __shared__ int   oldfin[KK];
    __shared__ float oldsc[KK];

    // merge the 125 colgroup partials for this warp's row
    {
        int row = b*KK + w;
        float m = -3.4e38f, s = 0.f;
        float tv[4] = {-3.4e38f, -3.4e38f, -3.4e38f, -3.4e38f};
        int   ti[4] = {0x7fffffff, 0x7fffffff, 0x7fffffff, 0x7fffffff};
        for (int c = l; c < NCG; c += 32) {
            int p = row*NCG + c;
            float pm = g_pmax[p], ps = g_psum[p];
            float M = fmaxf(m, pm);
            s = s*expf(m - M) + ps*expf(pm - M);
            m = M;
            float bv[4]; int bi[4];
            #pragma unroll
            for (int j = 0; j < 4; ++j) { bv[j] = g_pval[p*4+j]; bi[j] = g_pidx[p*4+j]; }
            merge4(tv, ti, bv, bi);
        }
        #pragma unroll
        for (int off = 16; off > 0; off >>= 1) {
            float pm = __shfl_xor_sync(0xffffffffu, m, off);
            float ps = __shfl_xor_sync(0xffffffffu, s, off);
            float M = fmaxf(m, pm);
            s = s*expf(m - M) + ps*expf(pm - M);
            m = M;
            float bv[4]; int bi[4];
            #pragma unroll
            for (int j = 0; j < 4; ++j) {
                bv[j] = __shfl_xor_sync(0xffffffffu, tv[j], off);
                bi[j] = __shfl_xor_sync(0xffffffffu, ti[j], off);
            }
            merge4(tv, ti, bv, bi);
        }
        if (l == 0) {
            s_lse[w] = m + logf(s);
            #pragma unroll
            for (int j = 0; j < 4; ++j) { s_tv[w][j] = tv[j]; s_ti[w][j] = ti[j]; }
        }
    }

    if (t < KK) { oldfin[t] = g_finished[b*KK + t]; oldsc[t] = g_scores[b*KK + t]; }
    for (int i = t; i < KK*TT; i += 128) oldseq[i >> 6][i & 63] = g_seqs[b*KK*TT + i];
    __syncthreads();

    if (tstep == 1) {
        // expand SOS (all beams identical; use k=0's row)
        if (t < KK) {
            int tok = s_ti[0][t];
            g_scores[b*KK + t]   = s_tv[0][t] - s_lse[0];
            g_tok[b*KK + t]      = tok;
            g_finished[b*KK + t] = (tok == EOS_TOK) ? 1 : 0;
        }
        for (int i = t; i < KK*TT; i += 128) {
            int k = i >> 6, j = i & 63;
            int v = (j == 0) ? SOS_TOK : (j == 1 ? s_ti[0][k] : PAD_TOK);
            g_seqs[b*KK*TT + i] = v;
        }
        return;
    }

    if (t == 0) {
        float cl[KK*KK]; int cv[KK*KK];
        for (int k = 0; k < KK; ++k) {
            if (oldfin[k]) {
                cl[k*KK+0] = 0.f; cv[k*KK+0] = PAD_TOK;
                for (int j = 1; j < KK; ++j) { cl[k*KK+j] = NEGV; cv[k*KK+j] = PAD_TOK; }
            } else {
                for (int j = 0; j < KK; ++j) {
                    cl[k*KK+j] = s_tv[k][j] - s_lse[k];
                    cv[k*KK+j] = s_ti[k][j];
                }
            }
        }
        float total[KK*KK];
        for (int i = 0; i < KK*KK; ++i) total[i] = oldsc[i >> 2] + cl[i];
        bool used[KK*KK] = {false};
        for (int k = 0; k < KK; ++k) {
            int best = -1;
            for (int i = 0; i < KK*KK; ++i)
                if (!used[i] && (best < 0 || total[i] > total[best])) best = i;
            used[best] = true;
            int beam = best >> 2;
            nbeam[k] = beam;
            ntok[k]  = cv[best];
            nsc[k]   = total[best];
            nfin[k]  = oldfin[beam] | (cv[best] == EOS_TOK ? 1 : 0);
        }
    }
    __syncthreads();

    if (t < KK) {
        g_scores[b*KK + t]   = nsc[t];
        g_finished[b*KK + t] = nfin[t];
        g_tok[b*KK + t]      = ntok[t];
    }
    for (int i = t; i < KK*TT; i += 128) {
        int k = i >> 6, j = i & 63;
        g_seqs[b*KK*TT + i] = (j == tstep) ? ntok[k] : oldseq[nbeam[k]][j];
    }
}

// ---------------- kernel 5: output ----------------
__global__ void out_kernel(float* __restrict__ out, int out_size) {
    int b = blockIdx.x;     // 16
    int t = threadIdx.x;    // 64
    __shared__ int best;
    __shared__ float bestsc;
    if (t == 0) {
        int bi = 0; float bs = g_scores[b*KK];
        for (int k = 1; k < KK; ++k)
            if (g_scores[b*KK + k] > bs) { bs = g_scores[b*KK + k]; bi = k; }
        best = bi; bestsc = bs;
    }
    __syncthreads();
    if (out_size >= BB*TT + BB) {
        out[b*TT + t] = (float)g_seqs[b*KK*TT + best*TT + t];
        if (t == 0) out[BB*TT + b] = bestsc;
    } else if (out_size == BB*TT) {
        out[b*TT + t] = (float)g_seqs[b*KK*TT + best*TT + t];
    } else if (out_size == BB) {
        if (t == 0) out[b] = bestsc;
    }
}

// ---------------- launcher ----------------
extern "C" void kernel_launch(void* const* d_in, const int* in_sizes, int n_in,
                              void* d_out, int out_size) {
    const float* enc  = (const float*)d_in[0];
    const int*   lens = (const int*)  d_in[1];
    const float* emb  = (const float*)d_in[2];
    const float* Wq   = (const float*)d_in[3];
    const float* Wk   = (const float*)d_in[4];
    const float* Wfc  = (const float*)d_in[5];
    const float* bfc  = (const float*)d_in[6];

    cudaFuncSetAttribute(logits_kernel, cudaFuncAttributeMaxDynamicSharedMemorySize, 65536);

    enck_kernel<<<BB*SS, 256>>>(enc, Wk);
    init_kernel<<<1, 64>>>();

    for (int step = 1; step < TT; ++step) {
        att_kernel<<<NR, 512>>>(enc, lens, emb, Wq);
        logits_kernel<<<2*NCG, 256, 65536>>>(Wfc, bfc);
        combine_kernel<<<BB, 128>>>(step);
    }

    out_kernel<<<BB, 64>>>((float*)d_out, out_size);
}